// round 1
// baseline (speedup 1.0000x reference)
#include <cuda_runtime.h>
#include <math_constants.h>

// Problem constants
#define BSZ   2
#define SEQ   2048
#define DIMM  1024
#define HEADS 16
#define HD    64
#define MROWS (BSZ*SEQ)      // 4096
#define QKVN  (3*DIMM)       // 3072

// Scratch (device globals: allocation-free rule)
__device__ float g_qT[BSZ*HEADS*HD*SEQ];   // [b,h,d,n]
__device__ float g_kT[BSZ*HEADS*HD*SEQ];   // [b,h,d,n]
__device__ float g_v [BSZ*HEADS*SEQ*HD];   // [b,h,n,d]
__device__ float g_ao[MROWS*DIMM];         // [b*n, h*hd]  attention output

// ---------------------------------------------------------------------------
// GEMM: C[m,e] = sum_k A[m,k]*B[e,k] + bias[e]
// 128x128 tile, K-tile 8, 256 threads, 8x8 per thread (2x2 of 4x4 blocks).
// MODE 0: A = x, scatter into g_qT/g_kT/g_v (QKV projection)
// MODE 1: A = g_ao, store into C (output projection)
// ---------------------------------------------------------------------------
template<int MODE>
__global__ __launch_bounds__(256) void gemm_nt_128(
    const float* __restrict__ A, const float* __restrict__ Bw,
    const float* __restrict__ bias, float* __restrict__ C)
{
    const int K = DIMM;
    __shared__ float As[8][128];
    __shared__ float Bs[8][128];

    const int t  = threadIdx.x;
    const int m0 = blockIdx.y * 128;
    const int n0 = blockIdx.x * 128;
    const int lr = t >> 1;
    const int lk = (t & 1) * 4;
    const int tx = t & 15;
    const int ty = t >> 4;

    const float* Ap = (MODE == 1) ? g_ao : A;
    const float* ag = Ap + (size_t)(m0 + lr) * K + lk;
    const float* bg = Bw + (size_t)(n0 + lr) * K + lk;

    float4 av = *(const float4*)ag;
    float4 bv = *(const float4*)bg;
    As[lk+0][lr]=av.x; As[lk+1][lr]=av.y; As[lk+2][lr]=av.z; As[lk+3][lr]=av.w;
    Bs[lk+0][lr]=bv.x; Bs[lk+1][lr]=bv.y; Bs[lk+2][lr]=bv.z; Bs[lk+3][lr]=bv.w;
    __syncthreads();

    float acc[8][8];
    #pragma unroll
    for (int i = 0; i < 8; i++)
        #pragma unroll
        for (int j = 0; j < 8; j++) acc[i][j] = 0.0f;

    const int KT = K / 8;   // 128
    for (int kt = 0; kt < KT; ++kt) {
        if (kt + 1 < KT) {
            av = *(const float4*)(ag + (kt + 1) * 8);
            bv = *(const float4*)(bg + (kt + 1) * 8);
        }
        #pragma unroll
        for (int kk = 0; kk < 8; ++kk) {
            float4 a0 = *(const float4*)&As[kk][ty*4];
            float4 a1 = *(const float4*)&As[kk][64 + ty*4];
            float4 b0 = *(const float4*)&Bs[kk][tx*4];
            float4 b1 = *(const float4*)&Bs[kk][64 + tx*4];
            float a[8] = {a0.x,a0.y,a0.z,a0.w,a1.x,a1.y,a1.z,a1.w};
            float b[8] = {b0.x,b0.y,b0.z,b0.w,b1.x,b1.y,b1.z,b1.w};
            #pragma unroll
            for (int i = 0; i < 8; i++)
                #pragma unroll
                for (int j = 0; j < 8; j++)
                    acc[i][j] = fmaf(a[i], b[j], acc[i][j]);
        }
        __syncthreads();
        if (kt + 1 < KT) {
            As[lk+0][lr]=av.x; As[lk+1][lr]=av.y; As[lk+2][lr]=av.z; As[lk+3][lr]=av.w;
            Bs[lk+0][lr]=bv.x; Bs[lk+1][lr]=bv.y; Bs[lk+2][lr]=bv.z; Bs[lk+3][lr]=bv.w;
            __syncthreads();
        }
    }

    // Epilogue
    #pragma unroll
    for (int i = 0; i < 8; i++) {
        const int m = m0 + ((i < 4) ? (ty*4 + i) : (64 + ty*4 + i - 4));
        #pragma unroll
        for (int j = 0; j < 8; j++) {
            const int e = n0 + ((j < 4) ? (tx*4 + j) : (64 + tx*4 + j - 4));
            float val = acc[i][j] + bias[e];
            if (MODE == 0) {
                const int part = e >> 10;        // 0=q 1=k 2=v
                const int dd   = e & 1023;
                const int h    = dd >> 6;
                const int d    = dd & 63;
                const int bb   = m >> 11;
                const int n    = m & 2047;
                if (part == 0)
                    g_qT[(((size_t)(bb*HEADS + h))*HD + d)*SEQ + n] = val;
                else if (part == 1)
                    g_kT[(((size_t)(bb*HEADS + h))*HD + d)*SEQ + n] = val;
                else
                    g_v [(((size_t)(bb*HEADS + h))*SEQ + n)*HD + d] = val;
            } else {
                C[(size_t)m * DIMM + e] = val;
            }
        }
    }
}

// ---------------------------------------------------------------------------
// Flash attention: per (b,h) and 64-row query block.
// Qt[d][m], Kt[d][n] (aliased with Ps[m][n]), Vs[n][d]; all 64x64 stride 64.
// Online softmax with shfl reductions (rows live on 16-lane groups).
// ---------------------------------------------------------------------------
__global__ __launch_bounds__(256) void flash_kernel()
{
    __shared__ float Qt[64][64];   // [d][m]
    __shared__ float KP[64][64];   // Kt[d][n], later reused as Ps[m][n]
    __shared__ float Vs[64][64];   // [n][d]

    const int t  = threadIdx.x;
    const int tx = t & 15;
    const int ty = t >> 4;
    const int bh = blockIdx.x;           // 0..31
    const int i0 = blockIdx.y;           // query block 0..31
    const size_t tbase = (size_t)bh * HD * SEQ;   // for qT / kT
    const size_t vbase = (size_t)bh * SEQ * HD;

    // Load Q tile once: Qt[d][m] = qT[bh][d][i0*64 + m]
    #pragma unroll
    for (int it = 0; it < 4; ++it) {
        int u  = t + it * 256;
        int dd = u >> 4;
        int m4 = (u & 15) * 4;
        *(float4*)&Qt[dd][m4] =
            *(const float4*)&g_qT[tbase + (size_t)dd * SEQ + i0*64 + m4];
    }

    float mi[4], li[4], o[4][4];
    #pragma unroll
    for (int i = 0; i < 4; i++) {
        mi[i] = -CUDART_INF_F; li[i] = 0.0f;
        #pragma unroll
        for (int j = 0; j < 4; j++) o[i][j] = 0.0f;
    }

    for (int jb = 0; jb < SEQ/64; ++jb) {
        __syncthreads();  // protect KP (prev Ps) and Vs still being read
        // K tile: KP[d][n] = kT[bh][d][jb*64+n]
        #pragma unroll
        for (int it = 0; it < 4; ++it) {
            int u = t + it * 256;
            int dd = u >> 4, m4 = (u & 15) * 4;
            *(float4*)&KP[dd][m4] =
                *(const float4*)&g_kT[tbase + (size_t)dd * SEQ + jb*64 + m4];
        }
        // V tile: Vs[n][d] = v[bh][jb*64+n][d]
        #pragma unroll
        for (int it = 0; it < 4; ++it) {
            int u = t + it * 256;
            int n = u >> 4, d4 = (u & 15) * 4;
            *(float4*)&Vs[n][d4] =
                *(const float4*)&g_v[vbase + (size_t)(jb*64 + n) * HD + d4];
        }
        __syncthreads();

        // S = (Q K^T) * scale  — 4x4 per thread
        float s[4][4];
        #pragma unroll
        for (int i = 0; i < 4; i++)
            #pragma unroll
            for (int j = 0; j < 4; j++) s[i][j] = 0.0f;

        #pragma unroll 16
        for (int kk = 0; kk < 64; ++kk) {
            float4 qa = *(const float4*)&Qt[kk][ty*4];
            float4 kb = *(const float4*)&KP[kk][tx*4];
            float a[4] = {qa.x, qa.y, qa.z, qa.w};
            float b[4] = {kb.x, kb.y, kb.z, kb.w};
            #pragma unroll
            for (int i = 0; i < 4; i++)
                #pragma unroll
                for (int j = 0; j < 4; j++)
                    s[i][j] = fmaf(a[i], b[j], s[i][j]);
        }

        // Online softmax update
        #pragma unroll
        for (int i = 0; i < 4; i++) {
            float rm = -CUDART_INF_F;
            #pragma unroll
            for (int j = 0; j < 4; j++) {
                s[i][j] *= 0.125f;
                rm = fmaxf(rm, s[i][j]);
            }
            #pragma unroll
            for (int off = 8; off > 0; off >>= 1)
                rm = fmaxf(rm, __shfl_xor_sync(0xffffffffu, rm, off));
            float mn = fmaxf(mi[i], rm);
            float corr = __expf(mi[i] - mn);
            mi[i] = mn;
            float rs = 0.0f;
            #pragma unroll
            for (int j = 0; j < 4; j++) {
                float p = __expf(s[i][j] - mn);
                s[i][j] = p;
                rs += p;
            }
            #pragma unroll
            for (int off = 8; off > 0; off >>= 1)
                rs += __shfl_xor_sync(0xffffffffu, rs, off);
            li[i] = li[i] * corr + rs;
            #pragma unroll
            for (int j = 0; j < 4; j++) o[i][j] *= corr;
        }

        __syncthreads();   // done reading Kt, safe to overwrite as Ps
        #pragma unroll
        for (int i = 0; i < 4; i++)
            #pragma unroll
            for (int j = 0; j < 4; j++)
                KP[ty*4 + i][tx*4 + j] = s[i][j];
        __syncthreads();

        // O += P @ V  — chunk n by 4 for float4 frag loads
        #pragma unroll
        for (int nn0 = 0; nn0 < 64; nn0 += 4) {
            float4 pa[4];
            #pragma unroll
            for (int i = 0; i < 4; i++)
                pa[i] = *(const float4*)&KP[ty*4 + i][nn0];
            #pragma unroll
            for (int jj = 0; jj < 4; jj++) {
                float4 vb = *(const float4*)&Vs[nn0 + jj][tx*4];
                float p0 = (jj==0)?pa[0].x:(jj==1)?pa[0].y:(jj==2)?pa[0].z:pa[0].w;
                float p1 = (jj==0)?pa[1].x:(jj==1)?pa[1].y:(jj==2)?pa[1].z:pa[1].w;
                float p2 = (jj==0)?pa[2].x:(jj==1)?pa[2].y:(jj==2)?pa[2].z:pa[2].w;
                float p3 = (jj==0)?pa[3].x:(jj==1)?pa[3].y:(jj==2)?pa[3].z:pa[3].w;
                o[0][0]=fmaf(p0,vb.x,o[0][0]); o[0][1]=fmaf(p0,vb.y,o[0][1]);
                o[0][2]=fmaf(p0,vb.z,o[0][2]); o[0][3]=fmaf(p0,vb.w,o[0][3]);
                o[1][0]=fmaf(p1,vb.x,o[1][0]); o[1][1]=fmaf(p1,vb.y,o[1][1]);
                o[1][2]=fmaf(p1,vb.z,o[1][2]); o[1][3]=fmaf(p1,vb.w,o[1][3]);
                o[2][0]=fmaf(p2,vb.x,o[2][0]); o[2][1]=fmaf(p2,vb.y,o[2][1]);
                o[2][2]=fmaf(p2,vb.z,o[2][2]); o[2][3]=fmaf(p2,vb.w,o[2][3]);
                o[3][0]=fmaf(p3,vb.x,o[3][0]); o[3][1]=fmaf(p3,vb.y,o[3][1]);
                o[3][2]=fmaf(p3,vb.z,o[3][2]); o[3][3]=fmaf(p3,vb.w,o[3][3]);
            }
        }
    }

    // Write: ao[b][n][h*64 + d]
    const int bb = bh >> 4;
    const int h  = bh & 15;
    #pragma unroll
    for (int i = 0; i < 4; i++) {
        float inv = 1.0f / li[i];
        int n = i0*64 + ty*4 + i;
        float4 r;
        r.x = o[i][0]*inv; r.y = o[i][1]*inv; r.z = o[i][2]*inv; r.w = o[i][3]*inv;
        *(float4*)&g_ao[((size_t)(bb*SEQ + n))*DIMM + h*HD + tx*4] = r;
    }
}

// ---------------------------------------------------------------------------
extern "C" void kernel_launch(void* const* d_in, const int* in_sizes, int n_in,
                              void* d_out, int out_size)
{
    const float* x     = (const float*)d_in[0];
    const float* W_qkv = (const float*)d_in[1];
    const float* b_qkv = (const float*)d_in[2];
    const float* W_out = (const float*)d_in[3];
    const float* b_out = (const float*)d_in[4];
    float* out = (float*)d_out;

    // 1) QKV projection + bias, scattered into transposed q/k and natural v
    gemm_nt_128<0><<<dim3(QKVN/128, MROWS/128), 256>>>(x, W_qkv, b_qkv, nullptr);
    // 2) Flash attention per (b,h) x query-block
    flash_kernel<<<dim3(BSZ*HEADS, SEQ/64), 256>>>();
    // 3) Output projection + bias
    gemm_nt_128<1><<<dim3(DIMM/128, MROWS/128), 256>>>(nullptr, W_out, b_out, out);
}

// round 4
// speedup vs baseline: 1.5425x; 1.5425x over previous
#include <cuda_runtime.h>
#include <cstdint>
#include <math_constants.h>

// Problem constants
#define BSZ   2
#define SEQ   2048
#define DIMM  1024
#define HEADS 16
#define HD    64
#define MROWS (BSZ*SEQ)      // 4096
#define QKVN  (3*DIMM)       // 3072
#define BH    (BSZ*HEADS)    // 32

// Scratch (device globals: allocation-free rule)
__device__ float g_q [BH*SEQ*HD];   // [bh][n][d]  (pre-scaled by 1/8)
__device__ float g_k [BH*SEQ*HD];   // [bh][n][d]
__device__ float g_vT[BH*HD*SEQ];   // [bh][d][n]
__device__ float g_ao[MROWS*DIMM];  // [b*n][h*64+d]

// ---------------------------------------------------------------------------
// helpers
// ---------------------------------------------------------------------------
__device__ __forceinline__ uint32_t smem_u32(const void* p) {
    uint32_t a;
    asm("{ .reg .u64 t; cvta.to.shared.u64 t, %1; cvt.u32.u64 %0, t; }"
        : "=r"(a) : "l"(p));
    return a;
}
__device__ __forceinline__ void cp16(uint32_t dst, const void* src) {
    asm volatile("cp.async.cg.shared.global [%0], [%1], 16;"
                 :: "r"(dst), "l"(src) : "memory");
}
#define CP_COMMIT() asm volatile("cp.async.commit_group;" ::: "memory")
#define CP_WAIT(n)  asm volatile("cp.async.wait_group %0;" :: "n"(n) : "memory")

__device__ __forceinline__ void ldsm4(uint32_t& r0, uint32_t& r1, uint32_t& r2,
                                      uint32_t& r3, uint32_t a) {
    asm volatile("ldmatrix.sync.aligned.m8n8.x4.shared.b16 {%0,%1,%2,%3}, [%4];"
                 : "=r"(r0), "=r"(r1), "=r"(r2), "=r"(r3) : "r"(a));
}
// mma m16n8k8 tf32: D(f32) += A(tf32) * B(tf32)
__device__ __forceinline__ void mma8(float* c, const uint32_t* a, const uint32_t* b) {
    asm volatile(
        "mma.sync.aligned.m16n8k8.row.col.f32.tf32.tf32.f32 "
        "{%0,%1,%2,%3},{%4,%5,%6,%7},{%8,%9},{%0,%1,%2,%3};"
        : "+f"(c[0]), "+f"(c[1]), "+f"(c[2]), "+f"(c[3])
        : "r"(a[0]), "r"(a[1]), "r"(a[2]), "r"(a[3]), "r"(b[0]), "r"(b[1]));
}
__device__ __forceinline__ uint32_t sw128(uint32_t o) { return o ^ ((o >> 3) & 0x70); } // 128B rows
__device__ __forceinline__ uint32_t sw256(uint32_t o) { return o ^ ((o >> 4) & 0x70); } // 256B rows

// tf32 split: x = hi + lo,  hi = round-to-nearest tf32(x), lo exact in fp32
__device__ __forceinline__ uint32_t tf32_rna(float x) {
    uint32_t h;
    asm("cvt.rna.tf32.f32 %0, %1;" : "=r"(h) : "f"(x));
    return h;
}
__device__ __forceinline__ void split4(const uint32_t* raw, uint32_t* hi, uint32_t* lo) {
    #pragma unroll
    for (int i = 0; i < 4; i++) {
        float x = __uint_as_float(raw[i]);
        uint32_t h = tf32_rna(x);
        hi[i] = h;
        lo[i] = __float_as_uint(x - __uint_as_float(h));
    }
}
__device__ __forceinline__ void rna4(uint32_t* r) {
    #pragma unroll
    for (int i = 0; i < 4; i++) r[i] = tf32_rna(__uint_as_float(r[i]));
}

// ---------------------------------------------------------------------------
// 3xTF32 GEMM: C[m,e] = sum_k A[m,k] * W[e,k] + bias[e]   (near-fp32 accurate)
// 128x128 tile, K-tile 32 (f32, 128B rows, SW128), 3-stage cp.async, 256 thr.
// MODE 0: A = x, scatter into g_q (x0.125) / g_k / g_vT.  MODE 1: A = g_ao -> C.
// ---------------------------------------------------------------------------
#define GSTAGES 3
#define GSTG    32768                     // 16KB A + 16KB B per stage
#define GEMM_SMEM (GSTAGES * GSTG)        // 96KB (also holds Ds 128x129 f32 = 66KB)

template<int MODE>
__global__ __launch_bounds__(256, 1) void gemm_tc(
    const float* __restrict__ Ain, const float* __restrict__ Bw,
    const float* __restrict__ bias, float* __restrict__ C)
{
    extern __shared__ float smem_f[];
    const uint32_t base = smem_u32(smem_f);
    const int t = threadIdx.x, lane = t & 31, wid = t >> 5;
    const int wm = wid >> 2, wn = wid & 3;      // 2 x 4 warp grid
    const int m0 = blockIdx.y * 128, n0 = blockIdx.x * 128;
    const float* A = (MODE == 1) ? g_ao : Ain;

    auto load_stage = [&](int kt) {
        uint32_t sA = base + (kt % GSTAGES) * GSTG;
        uint32_t sB = sA + 16384;
        const float* ag = A  + (size_t)m0 * DIMM + kt * 32;
        const float* bg = Bw + (size_t)n0 * DIMM + kt * 32;
        #pragma unroll
        for (int i = 0; i < 4; i++) {
            int u = t + i * 256;                // 0..1023
            int r = u >> 3, c = u & 7;          // row, 16B col
            uint32_t sw = sw128((uint32_t)(r * 128 + c * 16));
            cp16(sA + sw, ag + (size_t)r * DIMM + c * 4);
            cp16(sB + sw, bg + (size_t)r * DIMM + c * 4);
        }
        CP_COMMIT();
    };

    float acc[4][4][4];
    #pragma unroll
    for (int mt = 0; mt < 4; mt++)
        #pragma unroll
        for (int nt = 0; nt < 4; nt++)
            #pragma unroll
            for (int i = 0; i < 4; i++) acc[mt][nt][i] = 0.0f;

    load_stage(0);
    load_stage(1);

    const int KT = DIMM / 32;   // 32
    for (int kt = 0; kt < KT; ++kt) {
        if (kt + 2 < KT) { load_stage(kt + 2); CP_WAIT(2); }
        else             { CP_WAIT(0); }
        __syncthreads();
        uint32_t sA = base + (kt % GSTAGES) * GSTG;
        uint32_t sB = sA + 16384;
        #pragma unroll
        for (int ks = 0; ks < 4; ++ks) {        // k8 steps
            uint32_t ahi[4][4], alo[4][4];
            #pragma unroll
            for (int mt = 0; mt < 4; mt++) {
                uint32_t raw[4];
                int row = wm * 64 + mt * 16 + (lane & 15);
                int c16 = ks * 2 + (lane >> 4);
                ldsm4(raw[0], raw[1], raw[2], raw[3],
                      sA + sw128((uint32_t)(row * 128 + c16 * 16)));
                split4(raw, ahi[mt], alo[mt]);
            }
            #pragma unroll
            for (int g = 0; g < 2; g++) {       // n16 groups
                uint32_t braw[4], bhi[4], blo[4];
                int row = wn * 32 + g * 16 + (lane & 7) + ((lane & 16) ? 8 : 0);
                int c16 = ks * 2 + ((lane & 8) ? 1 : 0);
                ldsm4(braw[0], braw[1], braw[2], braw[3],
                      sB + sw128((uint32_t)(row * 128 + c16 * 16)));
                split4(braw, bhi, blo);
                #pragma unroll
                for (int mt = 0; mt < 4; mt++) {
                    mma8(acc[mt][2*g],     ahi[mt], bhi);
                    mma8(acc[mt][2*g],     alo[mt], bhi);
                    mma8(acc[mt][2*g],     ahi[mt], blo);
                    mma8(acc[mt][2*g + 1], ahi[mt], bhi + 2);
                    mma8(acc[mt][2*g + 1], alo[mt], bhi + 2);
                    mma8(acc[mt][2*g + 1], ahi[mt], blo + 2);
                }
            }
        }
        __syncthreads();
    }

    // ------------------------------ epilogue ------------------------------
    const int r  = lane >> 2;
    const int c2 = (lane & 3) * 2;

    if (MODE == 1) {
        #pragma unroll
        for (int mt = 0; mt < 4; mt++) {
            int m = m0 + wm * 64 + mt * 16 + r;
            #pragma unroll
            for (int nt = 0; nt < 4; nt++) {
                int e = n0 + wn * 32 + nt * 8 + c2;
                float2 bb = *(const float2*)&bias[e];
                float2 v0 = { acc[mt][nt][0] + bb.x, acc[mt][nt][1] + bb.y };
                float2 v1 = { acc[mt][nt][2] + bb.x, acc[mt][nt][3] + bb.y };
                *(float2*)&C[(size_t)m * DIMM + e]       = v0;
                *(float2*)&C[(size_t)(m + 8) * DIMM + e] = v1;
            }
        }
    } else {
        const int part = n0 >> 10;              // 0=q 1=k 2=v
        if (part < 2) {
            float* dst = part ? g_k : g_q;
            const float sc = part ? 1.0f : 0.125f;
            #pragma unroll
            for (int mt = 0; mt < 4; mt++) {
                int m = m0 + wm * 64 + mt * 16 + r;
                int bb_ = m >> 11, nloc = m & 2047;
                #pragma unroll
                for (int nt = 0; nt < 4; nt++) {
                    int eg = n0 + wn * 32 + nt * 8 + c2;
                    float2 bv = *(const float2*)&bias[eg];
                    int e = eg & 1023;
                    int h = e >> 6, d = e & 63;
                    size_t o = ((size_t)((bb_ * HEADS + h) * SEQ + nloc)) * HD + d;
                    float2 v0 = { (acc[mt][nt][0] + bv.x) * sc, (acc[mt][nt][1] + bv.y) * sc };
                    float2 v1 = { (acc[mt][nt][2] + bv.x) * sc, (acc[mt][nt][3] + bv.y) * sc };
                    *(float2*)&dst[o]          = v0;
                    *(float2*)&dst[o + 8 * HD] = v1;
                }
            }
        } else {
            // v: bounce via smem, write transposed g_vT[d][n]
            float* Ds = smem_f;                  // [128][129]
            #pragma unroll
            for (int mt = 0; mt < 4; mt++) {
                int ml = wm * 64 + mt * 16 + r;
                #pragma unroll
                for (int nt = 0; nt < 4; nt++) {
                    int el = wn * 32 + nt * 8 + c2;
                    float2 bv = *(const float2*)&bias[n0 + el];
                    Ds[ml * 129 + el]           = acc[mt][nt][0] + bv.x;
                    Ds[ml * 129 + el + 1]       = acc[mt][nt][1] + bv.y;
                    Ds[(ml + 8) * 129 + el]     = acc[mt][nt][2] + bv.x;
                    Ds[(ml + 8) * 129 + el + 1] = acc[mt][nt][3] + bv.y;
                }
            }
            __syncthreads();
            int e  = t >> 1;                     // 0..127  (d index within tile)
            int mh = (t & 1) * 64;
            int dg = (n0 & 1023) + e;
            int h = dg >> 6, d = dg & 63;
            int bb_ = m0 >> 11, nloc = m0 & 2047;
            float* dst = &g_vT[((size_t)((bb_ * HEADS + h) * HD + d)) * SEQ + nloc + mh];
            #pragma unroll 4
            for (int i = 0; i < 64; i += 4) {
                float4 v = { Ds[(mh + i) * 129 + e],     Ds[(mh + i + 1) * 129 + e],
                             Ds[(mh + i + 2) * 129 + e], Ds[(mh + i + 3) * 129 + e] };
                *(float4*)&dst[i] = v;
            }
        }
    }
}

// ---------------------------------------------------------------------------
// Flash attention, tf32 mma (QK: 3xTF32, PV: split-P x2). CTA = 64 q-rows.
// Qs[64][64], Ks[2][64][64] (n-major), Vt[2][64][64] (d-major); 256B rows.
// ---------------------------------------------------------------------------
#define F_SMEM (5 * 16384)   // Qs + 2*Ks + 2*Vt = 80KB

__global__ __launch_bounds__(128) void flash_kernel()
{
    extern __shared__ float fs[];
    const uint32_t base = smem_u32(fs);
    const uint32_t Qs  = base;
    const uint32_t Ks0 = base + 16384;
    const uint32_t Vt0 = base + 3 * 16384;

    const int t = threadIdx.x, lane = t & 31, w = t >> 5;
    const int bh = blockIdx.x, i0 = blockIdx.y;
    const int r = lane >> 2, q = lane & 3;

    // Q tile (once)
    {
        const float* qg = g_q + ((size_t)bh * SEQ + i0 * 64) * HD;
        #pragma unroll
        for (int i = 0; i < 8; i++) {
            int u = t + i * 128;
            int rr = u >> 4, c = u & 15;
            cp16(Qs + sw256((uint32_t)(rr * 256 + c * 16)), qg + (size_t)rr * HD + c * 4);
        }
        CP_COMMIT();
    }
    auto loadKV = [&](int j) {
        uint32_t sK = Ks0 + (j & 1) * 16384, sV = Vt0 + (j & 1) * 16384;
        const float* kg = g_k  + ((size_t)bh * SEQ + j * 64) * HD;
        const float* vg = g_vT + (size_t)bh * HD * SEQ + j * 64;
        #pragma unroll
        for (int i = 0; i < 8; i++) {
            int u = t + i * 128;
            int rr = u >> 4, c = u & 15;
            uint32_t sw = sw256((uint32_t)(rr * 256 + c * 16));
            cp16(sK + sw, kg + (size_t)rr * HD + c * 4);
            cp16(sV + sw, vg + (size_t)rr * SEQ + c * 4);
        }
        CP_COMMIT();
    };
    loadKV(0);

    float oacc[8][4];
    #pragma unroll
    for (int d = 0; d < 8; d++)
        #pragma unroll
        for (int i = 0; i < 4; i++) oacc[d][i] = 0.0f;
    float mrow[2] = { -CUDART_INF_F, -CUDART_INF_F };
    float lrow[2] = { 0.0f, 0.0f };

    const int srcA = (lane & ~3) | (q >> 1);
    const int srcB = srcA | 2;

    for (int j = 0; j < SEQ / 64; ++j) {
        if (j + 1 < SEQ / 64) { loadKV(j + 1); CP_WAIT(1); }
        else                  { CP_WAIT(0); }
        __syncthreads();
        const uint32_t sK = Ks0 + (j & 1) * 16384;
        const uint32_t sV = Vt0 + (j & 1) * 16384;

        // ---- S = Q K^T (scale folded into Q), 3xTF32 ----
        float sacc[8][4];
        #pragma unroll
        for (int nt = 0; nt < 8; nt++)
            #pragma unroll
            for (int i = 0; i < 4; i++) sacc[nt][i] = 0.0f;

        #pragma unroll
        for (int ks = 0; ks < 8; ++ks) {
            uint32_t ahi[4], alo[4];
            {
                uint32_t raw[4];
                int row = w * 16 + (lane & 15);
                int c16 = ks * 2 + (lane >> 4);
                ldsm4(raw[0], raw[1], raw[2], raw[3],
                      Qs + sw256((uint32_t)(row * 256 + c16 * 16)));
                split4(raw, ahi, alo);
            }
            #pragma unroll
            for (int g = 0; g < 4; g++) {
                uint32_t braw[4], bhi[4], blo[4];
                int row = g * 16 + (lane & 7) + ((lane & 16) ? 8 : 0);
                int c16 = ks * 2 + ((lane & 8) ? 1 : 0);
                ldsm4(braw[0], braw[1], braw[2], braw[3],
                      sK + sw256((uint32_t)(row * 256 + c16 * 16)));
                split4(braw, bhi, blo);
                mma8(sacc[2*g],     ahi, bhi);
                mma8(sacc[2*g],     alo, bhi);
                mma8(sacc[2*g],     ahi, blo);
                mma8(sacc[2*g + 1], ahi, bhi + 2);
                mma8(sacc[2*g + 1], alo, bhi + 2);
                mma8(sacc[2*g + 1], ahi, blo + 2);
            }
        }

        // ---- online softmax ----
        #pragma unroll
        for (int rp = 0; rp < 2; rp++) {
            const int lo = rp * 2;
            float mx = -CUDART_INF_F;
            #pragma unroll
            for (int nt = 0; nt < 8; nt++)
                mx = fmaxf(mx, fmaxf(sacc[nt][lo], sacc[nt][lo + 1]));
            mx = fmaxf(mx, __shfl_xor_sync(0xffffffffu, mx, 1));
            mx = fmaxf(mx, __shfl_xor_sync(0xffffffffu, mx, 2));
            float mn = fmaxf(mrow[rp], mx);
            float corr = __expf(mrow[rp] - mn);
            mrow[rp] = mn;
            float sum = 0.0f;
            #pragma unroll
            for (int nt = 0; nt < 8; nt++) {
                float p0 = __expf(sacc[nt][lo] - mn);
                float p1 = __expf(sacc[nt][lo + 1] - mn);
                sacc[nt][lo] = p0; sacc[nt][lo + 1] = p1;
                sum += p0 + p1;
            }
            sum += __shfl_xor_sync(0xffffffffu, sum, 1);
            sum += __shfl_xor_sync(0xffffffffu, sum, 2);
            lrow[rp] = lrow[rp] * corr + sum;
            #pragma unroll
            for (int d = 0; d < 8; d++) {
                oacc[d][lo]     *= corr;
                oacc[d][lo + 1] *= corr;
            }
        }

        // ---- O += P V  (P split x2, V round-to-nearest tf32) ----
        #pragma unroll
        for (int ks = 0; ks < 8; ++ks) {
            float t00 = __shfl_sync(0xffffffffu, sacc[ks][0], srcA);
            float t10 = __shfl_sync(0xffffffffu, sacc[ks][1], srcA);
            float t20 = __shfl_sync(0xffffffffu, sacc[ks][2], srcA);
            float t30 = __shfl_sync(0xffffffffu, sacc[ks][3], srcA);
            float t01 = __shfl_sync(0xffffffffu, sacc[ks][0], srcB);
            float t11 = __shfl_sync(0xffffffffu, sacc[ks][1], srcB);
            float t21 = __shfl_sync(0xffffffffu, sacc[ks][2], srcB);
            float t31 = __shfl_sync(0xffffffffu, sacc[ks][3], srcB);
            uint32_t pa[4], pahi[4], palo[4];
            pa[0] = __float_as_uint((q & 1) ? t10 : t00);   // P[r][c]
            pa[1] = __float_as_uint((q & 1) ? t30 : t20);   // P[r+8][c]
            pa[2] = __float_as_uint((q & 1) ? t11 : t01);   // P[r][c+4]
            pa[3] = __float_as_uint((q & 1) ? t31 : t21);   // P[r+8][c+4]
            split4(pa, pahi, palo);
            #pragma unroll
            for (int g = 0; g < 4; g++) {
                uint32_t b[4];
                int row = g * 16 + (lane & 7) + ((lane & 16) ? 8 : 0);
                int c16 = ks * 2 + ((lane & 8) ? 1 : 0);
                ldsm4(b[0], b[1], b[2], b[3],
                      sV + sw256((uint32_t)(row * 256 + c16 * 16)));
                rna4(b);
                mma8(oacc[2*g],     pahi, b);
                mma8(oacc[2*g],     palo, b);
                mma8(oacc[2*g + 1], pahi, b + 2);
                mma8(oacc[2*g + 1], palo, b + 2);
            }
        }
        __syncthreads();
    }

    // ---- write O / l ----
    const int bb = bh >> 4, h = bh & 15;
    #pragma unroll
    for (int rp = 0; rp < 2; rp++) {
        float inv = 1.0f / lrow[rp];
        int n = i0 * 64 + w * 16 + r + rp * 8;
        float* dst = &g_ao[((size_t)(bb * SEQ + n)) * DIMM + h * 64];
        #pragma unroll
        for (int d = 0; d < 8; d++) {
            float2 v = { oacc[d][rp * 2] * inv, oacc[d][rp * 2 + 1] * inv };
            *(float2*)&dst[d * 8 + q * 2] = v;
        }
    }
}

// ---------------------------------------------------------------------------
extern "C" void kernel_launch(void* const* d_in, const int* in_sizes, int n_in,
                              void* d_out, int out_size)
{
    const float* x     = (const float*)d_in[0];
    const float* W_qkv = (const float*)d_in[1];
    const float* b_qkv = (const float*)d_in[2];
    const float* W_out = (const float*)d_in[3];
    const float* b_out = (const float*)d_in[4];
    float* out = (float*)d_out;

    cudaFuncSetAttribute(gemm_tc<0>, cudaFuncAttributeMaxDynamicSharedMemorySize, GEMM_SMEM);
    cudaFuncSetAttribute(gemm_tc<1>, cudaFuncAttributeMaxDynamicSharedMemorySize, GEMM_SMEM);
    cudaFuncSetAttribute(flash_kernel, cudaFuncAttributeMaxDynamicSharedMemorySize, F_SMEM);

    gemm_tc<0><<<dim3(QKVN/128, MROWS/128), 256, GEMM_SMEM>>>(x, W_qkv, b_qkv, nullptr);
    flash_kernel<<<dim3(BH, SEQ/64), 128, F_SMEM>>>();
    gemm_tc<1><<<dim3(DIMM/128, MROWS/128), 256, GEMM_SMEM>>>(nullptr, W_out, b_out, out);
}

// round 7
// speedup vs baseline: 2.6411x; 1.7123x over previous
#include <cuda_runtime.h>
#include <cuda_bf16.h>
#include <cstdint>
#include <math_constants.h>

// Problem constants
#define BSZ   2
#define SEQ   2048
#define DIMM  1024
#define HEADS 16
#define HD    64
#define MROWS (BSZ*SEQ)      // 4096
#define QKVN  (3*DIMM)       // 3072
#define BH    (BSZ*HEADS)    // 32

// Scratch (device globals: allocation-free rule)
__device__ __nv_bfloat16 g_q_h [BH*SEQ*HD];  // [bh][n][d] hi (pre-scaled 1/8)
__device__ __nv_bfloat16 g_q_l [BH*SEQ*HD];  // lo
__device__ __nv_bfloat16 g_k_h [BH*SEQ*HD];  // [bh][n][d]
__device__ __nv_bfloat16 g_k_l [BH*SEQ*HD];
__device__ __nv_bfloat16 g_vT_h[BH*HD*SEQ];  // [bh][d][n]
__device__ __nv_bfloat16 g_vT_l[BH*HD*SEQ];
__device__ float g_ao[MROWS*DIMM];           // [b*n][h*64+d]

// ---------------------------------------------------------------------------
// helpers
// ---------------------------------------------------------------------------
__device__ __forceinline__ uint32_t smem_u32(const void* p) {
    uint32_t a;
    asm("{ .reg .u64 t; cvta.to.shared.u64 t, %1; cvt.u32.u64 %0, t; }"
        : "=r"(a) : "l"(p));
    return a;
}
__device__ __forceinline__ void cp16(uint32_t dst, const void* src) {
    asm volatile("cp.async.cg.shared.global [%0], [%1], 16;"
                 :: "r"(dst), "l"(src) : "memory");
}
#define CP_COMMIT() asm volatile("cp.async.commit_group;" ::: "memory")
#define CP_WAIT(n)  asm volatile("cp.async.wait_group %0;" :: "n"(n) : "memory")

__device__ __forceinline__ void ldsm4(uint32_t& r0, uint32_t& r1, uint32_t& r2,
                                      uint32_t& r3, uint32_t a) {
    asm volatile("ldmatrix.sync.aligned.m8n8.x4.shared.b16 {%0,%1,%2,%3}, [%4];"
                 : "=r"(r0), "=r"(r1), "=r"(r2), "=r"(r3) : "r"(a));
}
// mma m16n8k16 bf16: D(f32) += A(bf16) * B(bf16)
__device__ __forceinline__ void mma16(float* c, const uint32_t* a, const uint32_t* b) {
    asm volatile(
        "mma.sync.aligned.m16n8k16.row.col.f32.bf16.bf16.f32 "
        "{%0,%1,%2,%3},{%4,%5,%6,%7},{%8,%9},{%0,%1,%2,%3};"
        : "+f"(c[0]), "+f"(c[1]), "+f"(c[2]), "+f"(c[3])
        : "r"(a[0]), "r"(a[1]), "r"(a[2]), "r"(a[3]), "r"(b[0]), "r"(b[1]));
}
__device__ __forceinline__ uint32_t sw128(uint32_t o) { return o ^ ((o >> 3) & 0x70); }

// pack two floats to bf16x2: x0 -> lower 16 bits (k even), x1 -> upper
__device__ __forceinline__ uint32_t packbf(float x0, float x1) {
    uint32_t d;
    asm("cvt.rn.bf16x2.f32 %0, %1, %2;" : "=r"(d) : "f"(x1), "f"(x0));
    return d;
}
// split pair: h = bf16x2(hi parts), l = bf16x2(residuals), x = hi + lo exactly-ish
__device__ __forceinline__ void split2(float x0, float x1, uint32_t& h, uint32_t& l) {
    h = packbf(x0, x1);
    float f0 = __uint_as_float(h << 16);
    float f1 = __uint_as_float(h & 0xFFFF0000u);
    l = packbf(x0 - f0, x1 - f1);
}
__device__ __forceinline__ void sts64(uint32_t addr, uint32_t a, uint32_t b) {
    asm volatile("st.shared.v2.b32 [%0], {%1,%2};" :: "r"(addr), "r"(a), "r"(b) : "memory");
}

// ---------------------------------------------------------------------------
// 3xBF16 GEMM: C[m,e] = sum_k A[m,k] * W[e,k] + bias[e]
// 128x128 tile, K-tile 32. SMEM stage: A rows [hi 64B | lo 64B] (128B, sw128),
// same for B. Double-buffered LDG->split->STS. 256 threads, 8 warps (2x4).
// MODE 0: A = x, scatter bf16 hi/lo into g_q/g_k/g_vT.  MODE 1: A = g_ao -> C.
// ---------------------------------------------------------------------------
#define GSTG      32768                   // 16KB A + 16KB B per stage
#define GEMM_SMEM 66560                   // max(2 stages, Ds 128x129 f32)

template<int MODE>
__global__ __launch_bounds__(256, 1) void gemm_tc(
    const float* __restrict__ Ain, const float* __restrict__ Bw,
    const float* __restrict__ bias, float* __restrict__ C)
{
    extern __shared__ float smem_f[];
    const uint32_t base = smem_u32(smem_f);
    const int t = threadIdx.x, lane = t & 31, wid = t >> 5;
    const int wm = wid >> 2, wn = wid & 3;      // 2 x 4 warp grid
    const int m0 = blockIdx.y * 128, n0 = blockIdx.x * 128;
    const float* A = (MODE == 1) ? g_ao : Ain;

    float4 ra[4], rb[4];
    auto ldg_tile = [&](int kt) {
        const float* ag = A  + (size_t)m0 * DIMM + kt * 32;
        const float* bg = Bw + (size_t)n0 * DIMM + kt * 32;
        #pragma unroll
        for (int i = 0; i < 4; i++) {
            int u = t + i * 256;                 // 0..1023
            int r = u >> 3, c = u & 7;
            ra[i] = *(const float4*)(ag + (size_t)r * DIMM + c * 4);
            rb[i] = *(const float4*)(bg + (size_t)r * DIMM + c * 4);
        }
    };
    auto sts_tile = [&](int s) {
        uint32_t sA = base + s * GSTG, sB = sA + 16384;
        #pragma unroll
        for (int i = 0; i < 4; i++) {
            int u = t + i * 256;
            int r = u >> 3, c = u & 7;
            uint32_t h0, l0, h1, l1;
            split2(ra[i].x, ra[i].y, h0, l0);
            split2(ra[i].z, ra[i].w, h1, l1);
            sts64(sA + sw128((uint32_t)(r * 128 + c * 8)), h0, h1);
            sts64(sA + sw128((uint32_t)(r * 128 + 64 + c * 8)), l0, l1);
            split2(rb[i].x, rb[i].y, h0, l0);
            split2(rb[i].z, rb[i].w, h1, l1);
            sts64(sB + sw128((uint32_t)(r * 128 + c * 8)), h0, h1);
            sts64(sB + sw128((uint32_t)(r * 128 + 64 + c * 8)), l0, l1);
        }
    };

    float acc[4][4][4];
    #pragma unroll
    for (int mt = 0; mt < 4; mt++)
        #pragma unroll
        for (int nt = 0; nt < 4; nt++)
            #pragma unroll
            for (int i = 0; i < 4; i++) acc[mt][nt][i] = 0.0f;

    ldg_tile(0);
    sts_tile(0);
    __syncthreads();

    const int KT = DIMM / 32;   // 32
    for (int kt = 0; kt < KT; ++kt) {
        if (kt + 1 < KT) ldg_tile(kt + 1);

        uint32_t sA = base + (kt & 1) * GSTG, sB = sA + 16384;
        #pragma unroll
        for (int cc = 0; cc < 2; ++cc) {        // k16 chunks
            uint32_t ah[4][4], al[4][4];
            #pragma unroll
            for (int mt = 0; mt < 4; mt++) {
                int row = wm * 64 + mt * 16 + (lane & 15);
                uint32_t bc = cc * 32 + (lane >> 4) * 16;
                ldsm4(ah[mt][0], ah[mt][1], ah[mt][2], ah[mt][3],
                      sA + sw128((uint32_t)(row * 128) + bc));
                ldsm4(al[mt][0], al[mt][1], al[mt][2], al[mt][3],
                      sA + sw128((uint32_t)(row * 128) + 64 + bc));
            }
            #pragma unroll
            for (int g = 0; g < 2; g++) {       // n16 groups
                uint32_t bh4[4], bl4[4];
                int row = wn * 32 + g * 16 + (lane & 7) + ((lane & 16) ? 8 : 0);
                uint32_t bc = cc * 32 + ((lane & 8) ? 16 : 0);
                ldsm4(bh4[0], bh4[1], bh4[2], bh4[3],
                      sB + sw128((uint32_t)(row * 128) + bc));
                ldsm4(bl4[0], bl4[1], bl4[2], bl4[3],
                      sB + sw128((uint32_t)(row * 128) + 64 + bc));
                #pragma unroll
                for (int mt = 0; mt < 4; mt++) {
                    mma16(acc[mt][2*g],     ah[mt], bh4);
                    mma16(acc[mt][2*g],     al[mt], bh4);
                    mma16(acc[mt][2*g],     ah[mt], bl4);
                    mma16(acc[mt][2*g + 1], ah[mt], bh4 + 2);
                    mma16(acc[mt][2*g + 1], al[mt], bh4 + 2);
                    mma16(acc[mt][2*g + 1], ah[mt], bl4 + 2);
                }
            }
        }
        if (kt + 1 < KT) sts_tile((kt + 1) & 1);
        __syncthreads();
    }

    // ------------------------------ epilogue ------------------------------
    const int r  = lane >> 2;
    const int c2 = (lane & 3) * 2;

    if (MODE == 1) {
        #pragma unroll
        for (int mt = 0; mt < 4; mt++) {
            int m = m0 + wm * 64 + mt * 16 + r;
            #pragma unroll
            for (int nt = 0; nt < 4; nt++) {
                int e = n0 + wn * 32 + nt * 8 + c2;
                float2 bb = *(const float2*)&bias[e];
                float2 v0 = { acc[mt][nt][0] + bb.x, acc[mt][nt][1] + bb.y };
                float2 v1 = { acc[mt][nt][2] + bb.x, acc[mt][nt][3] + bb.y };
                *(float2*)&C[(size_t)m * DIMM + e]       = v0;
                *(float2*)&C[(size_t)(m + 8) * DIMM + e] = v1;
            }
        }
    } else {
        const int part = n0 >> 10;              // 0=q 1=k 2=v
        if (part < 2) {
            __nv_bfloat16* dh = part ? g_k_h : g_q_h;
            __nv_bfloat16* dl = part ? g_k_l : g_q_l;
            const float sc = part ? 1.0f : 0.125f;
            #pragma unroll
            for (int mt = 0; mt < 4; mt++) {
                int m = m0 + wm * 64 + mt * 16 + r;
                int bb_ = m >> 11, nloc = m & 2047;
                #pragma unroll
                for (int nt = 0; nt < 4; nt++) {
                    int eg = n0 + wn * 32 + nt * 8 + c2;
                    float2 bv = *(const float2*)&bias[eg];
                    int e = eg & 1023;
                    int h = e >> 6, d = e & 63;
                    size_t o = ((size_t)((bb_ * HEADS + h) * SEQ + nloc)) * HD + d;
                    uint32_t hh, ll;
                    split2((acc[mt][nt][0] + bv.x) * sc, (acc[mt][nt][1] + bv.y) * sc, hh, ll);
                    *(uint32_t*)&dh[o] = hh;
                    *(uint32_t*)&dl[o] = ll;
                    split2((acc[mt][nt][2] + bv.x) * sc, (acc[mt][nt][3] + bv.y) * sc, hh, ll);
                    *(uint32_t*)&dh[o + 8 * HD] = hh;
                    *(uint32_t*)&dl[o + 8 * HD] = ll;
                }
            }
        } else {
            // v: bounce fp32 via smem, transpose, split to g_vT hi/lo [d][n]
            float* Ds = smem_f;                  // [128][129]
            #pragma unroll
            for (int mt = 0; mt < 4; mt++) {
                int ml = wm * 64 + mt * 16 + r;
                #pragma unroll
                for (int nt = 0; nt < 4; nt++) {
                    int el = wn * 32 + nt * 8 + c2;
                    float2 bv = *(const float2*)&bias[n0 + el];
                    Ds[ml * 129 + el]           = acc[mt][nt][0] + bv.x;
                    Ds[ml * 129 + el + 1]       = acc[mt][nt][1] + bv.y;
                    Ds[(ml + 8) * 129 + el]     = acc[mt][nt][2] + bv.x;
                    Ds[(ml + 8) * 129 + el + 1] = acc[mt][nt][3] + bv.y;
                }
            }
            __syncthreads();
            int e  = t >> 1;                     // d index within tile (0..127)
            int mh = (t & 1) * 64;               // n half
            int dg = (n0 & 1023) + e;
            int h = dg >> 6, d = dg & 63;
            int bb_ = m0 >> 11, nloc = m0 & 2047;
            size_t ob = ((size_t)((bb_ * HEADS + h) * HD + d)) * SEQ + nloc + mh;
            #pragma unroll 4
            for (int i = 0; i < 64; i += 4) {
                uint32_t h0, l0, h1, l1;
                split2(Ds[(mh + i) * 129 + e],     Ds[(mh + i + 1) * 129 + e], h0, l0);
                split2(Ds[(mh + i + 2) * 129 + e], Ds[(mh + i + 3) * 129 + e], h1, l1);
                uint2 vh = { h0, h1 }, vl = { l0, l1 };
                *(uint2*)&g_vT_h[ob + i] = vh;
                *(uint2*)&g_vT_l[ob + i] = vl;
            }
        }
    }
}

// ---------------------------------------------------------------------------
// Flash attention, 3xBF16. CTA = 64 q-rows (4 warps, m16/warp), j-tile 64.
// SMEM planes (all [64 rows][128B], sw128): Qh, Ql; per stage: Kh, Kl, Vh, Vl.
// ---------------------------------------------------------------------------
#define F_SMEM (16384 + 2 * 32768)   // 80KB

__global__ __launch_bounds__(128) void flash_kernel()
{
    extern __shared__ float fs[];
    const uint32_t base = smem_u32(fs);
    const uint32_t Qh = base, Ql = base + 8192;
    const uint32_t St = base + 16384;            // stages

    const int t = threadIdx.x, lane = t & 31, w = t >> 5;
    const int bh = blockIdx.x, i0 = blockIdx.y;
    const int r = lane >> 2, q = lane & 3;

    // Q tile (once)
    {
        const __nv_bfloat16* qh = g_q_h + ((size_t)bh * SEQ + i0 * 64) * HD;
        const __nv_bfloat16* ql = g_q_l + ((size_t)bh * SEQ + i0 * 64) * HD;
        #pragma unroll
        for (int i = 0; i < 4; i++) {
            int u = t + i * 128;
            int rr = u >> 3, c = u & 7;
            uint32_t sw = sw128((uint32_t)(rr * 128 + c * 16));
            cp16(Qh + sw, qh + (size_t)rr * HD + c * 8);
            cp16(Ql + sw, ql + (size_t)rr * HD + c * 8);
        }
        CP_COMMIT();
    }
    auto loadKV = [&](int j) {
        uint32_t S = St + (j & 1) * 32768;
        const __nv_bfloat16* kh = g_k_h  + ((size_t)bh * SEQ + j * 64) * HD;
        const __nv_bfloat16* kl = g_k_l  + ((size_t)bh * SEQ + j * 64) * HD;
        const __nv_bfloat16* vh = g_vT_h + (size_t)bh * HD * SEQ + j * 64;
        const __nv_bfloat16* vl = g_vT_l + (size_t)bh * HD * SEQ + j * 64;
        #pragma unroll
        for (int i = 0; i < 4; i++) {
            int u = t + i * 128;
            int rr = u >> 3, c = u & 7;
            uint32_t sw = sw128((uint32_t)(rr * 128 + c * 16));
            cp16(S + sw,         kh + (size_t)rr * HD + c * 8);
            cp16(S + 8192 + sw,  kl + (size_t)rr * HD + c * 8);
            cp16(S + 16384 + sw, vh + (size_t)rr * SEQ + c * 8);
            cp16(S + 24576 + sw, vl + (size_t)rr * SEQ + c * 8);
        }
        CP_COMMIT();
    };
    loadKV(0);

    float oacc[8][4];
    #pragma unroll
    for (int d = 0; d < 8; d++)
        #pragma unroll
        for (int i = 0; i < 4; i++) oacc[d][i] = 0.0f;
    float mrow[2] = { -CUDART_INF_F, -CUDART_INF_F };
    float lrow[2] = { 0.0f, 0.0f };

    for (int j = 0; j < SEQ / 64; ++j) {
        if (j + 1 < SEQ / 64) { loadKV(j + 1); CP_WAIT(1); }
        else                  { CP_WAIT(0); }
        __syncthreads();
        const uint32_t sK = St + (j & 1) * 32768;
        const uint32_t sV = sK + 16384;

        // ---- S = Q K^T (scale folded into Q), 3xBF16 ----
        float sacc[8][4];
        #pragma unroll
        for (int nt = 0; nt < 8; nt++)
            #pragma unroll
            for (int i = 0; i < 4; i++) sacc[nt][i] = 0.0f;

        #pragma unroll
        for (int cc = 0; cc < 4; ++cc) {        // k16 over d=64
            uint32_t ah[4], al[4];
            {
                int row = w * 16 + (lane & 15);
                uint32_t bc = cc * 32 + (lane >> 4) * 16;
                ldsm4(ah[0], ah[1], ah[2], ah[3], Qh + sw128((uint32_t)(row * 128) + bc));
                ldsm4(al[0], al[1], al[2], al[3], Ql + sw128((uint32_t)(row * 128) + bc));
            }
            #pragma unroll
            for (int g = 0; g < 4; g++) {       // n16 over 64 keys
                uint32_t bh4[4], bl4[4];
                int row = g * 16 + (lane & 7) + ((lane & 16) ? 8 : 0);
                uint32_t bc = cc * 32 + ((lane & 8) ? 16 : 0);
                ldsm4(bh4[0], bh4[1], bh4[2], bh4[3],
                      sK + sw128((uint32_t)(row * 128) + bc));
                ldsm4(bl4[0], bl4[1], bl4[2], bl4[3],
                      sK + 8192 + sw128((uint32_t)(row * 128) + bc));
                mma16(sacc[2*g],     ah, bh4);
                mma16(sacc[2*g],     al, bh4);
                mma16(sacc[2*g],     ah, bl4);
                mma16(sacc[2*g + 1], ah, bh4 + 2);
                mma16(sacc[2*g + 1], al, bh4 + 2);
                mma16(sacc[2*g + 1], ah, bl4 + 2);
            }
        }

        // ---- online softmax ----
        #pragma unroll
        for (int rp = 0; rp < 2; rp++) {
            const int lo = rp * 2;
            float mx = -CUDART_INF_F;
            #pragma unroll
            for (int nt = 0; nt < 8; nt++)
                mx = fmaxf(mx, fmaxf(sacc[nt][lo], sacc[nt][lo + 1]));
            mx = fmaxf(mx, __shfl_xor_sync(0xffffffffu, mx, 1));
            mx = fmaxf(mx, __shfl_xor_sync(0xffffffffu, mx, 2));
            float mn = fmaxf(mrow[rp], mx);
            float corr = __expf(mrow[rp] - mn);
            mrow[rp] = mn;
            float sum = 0.0f;
            #pragma unroll
            for (int nt = 0; nt < 8; nt++) {
                float p0 = __expf(sacc[nt][lo] - mn);
                float p1 = __expf(sacc[nt][lo + 1] - mn);
                sacc[nt][lo] = p0; sacc[nt][lo + 1] = p1;
                sum += p0 + p1;
            }
            sum += __shfl_xor_sync(0xffffffffu, sum, 1);
            sum += __shfl_xor_sync(0xffffffffu, sum, 2);
            lrow[rp] = lrow[rp] * corr + sum;
            #pragma unroll
            for (int d = 0; d < 8; d++) {
                oacc[d][lo]     *= corr;
                oacc[d][lo + 1] *= corr;
            }
        }

        // ---- O += P V  (P split to bf16 hi/lo in-register: no shuffles) ----
        #pragma unroll
        for (int kc = 0; kc < 4; ++kc) {        // k16 over 64 keys
            uint32_t ph[4], pl[4];
            split2(sacc[2*kc][0],     sacc[2*kc][1],     ph[0], pl[0]);
            split2(sacc[2*kc][2],     sacc[2*kc][3],     ph[1], pl[1]);
            split2(sacc[2*kc + 1][0], sacc[2*kc + 1][1], ph[2], pl[2]);
            split2(sacc[2*kc + 1][2], sacc[2*kc + 1][3], ph[3], pl[3]);
            #pragma unroll
            for (int g = 0; g < 4; g++) {       // n16 over d=64
                uint32_t vh4[4], vl4[4];
                int row = g * 16 + (lane & 7) + ((lane & 16) ? 8 : 0);
                uint32_t bc = kc * 32 + ((lane & 8) ? 16 : 0);
                ldsm4(vh4[0], vh4[1], vh4[2], vh4[3],
                      sV + sw128((uint32_t)(row * 128) + bc));
                ldsm4(vl4[0], vl4[1], vl4[2], vl4[3],
                      sV + 8192 + sw128((uint32_t)(row * 128) + bc));
                mma16(oacc[2*g],     ph, vh4);
                mma16(oacc[2*g],     pl, vh4);
                mma16(oacc[2*g],     ph, vl4);
                mma16(oacc[2*g + 1], ph, vh4 + 2);
                mma16(oacc[2*g + 1], pl, vh4 + 2);
                mma16(oacc[2*g + 1], ph, vl4 + 2);
            }
        }
        __syncthreads();
    }

    // ---- write O / l ----
    const int bb = bh >> 4, h = bh & 15;
    #pragma unroll
    for (int rp = 0; rp < 2; rp++) {
        float inv = 1.0f / lrow[rp];
        int n = i0 * 64 + w * 16 + r + rp * 8;
        float* dst = &g_ao[((size_t)(bb * SEQ + n)) * DIMM + h * 64];
        #pragma unroll
        for (int d = 0; d < 8; d++) {
            float2 v = { oacc[d][rp * 2] * inv, oacc[d][rp * 2 + 1] * inv };
            *(float2*)&dst[d * 8 + q * 2] = v;
        }
    }
}

// ---------------------------------------------------------------------------
extern "C" void kernel_launch(void* const* d_in, const int* in_sizes, int n_in,
                              void* d_out, int out_size)
{
    const float* x     = (const float*)d_in[0];
    const float* W_qkv = (const float*)d_in[1];
    const float* b_qkv = (const float*)d_in[2];
    const float* W_out = (const float*)d_in[3];
    const float* b_out = (const float*)d_in[4];
    float* out = (float*)d_out;

    cudaFuncSetAttribute(gemm_tc<0>, cudaFuncAttributeMaxDynamicSharedMemorySize, GEMM_SMEM);
    cudaFuncSetAttribute(gemm_tc<1>, cudaFuncAttributeMaxDynamicSharedMemorySize, GEMM_SMEM);
    cudaFuncSetAttribute(flash_kernel, cudaFuncAttributeMaxDynamicSharedMemorySize, F_SMEM);

    gemm_tc<0><<<dim3(QKVN/128, MROWS/128), 256, GEMM_SMEM>>>(x, W_qkv, b_qkv, nullptr);
    flash_kernel<<<dim3(BH, SEQ/64), 128, F_SMEM>>>();
    gemm_tc<1><<<dim3(DIMM/128, MROWS/128), 256, GEMM_SMEM>>>(nullptr, W_out, b_out, out);
}

// round 8
// speedup vs baseline: 2.7944x; 1.0580x over previous
#include <cuda_runtime.h>
#include <cuda_bf16.h>
#include <cstdint>
#include <math_constants.h>

// Problem constants
#define BSZ   2
#define SEQ   2048
#define DIMM  1024
#define HEADS 16
#define HD    64
#define MROWS (BSZ*SEQ)      // 4096
#define QKVN  (3*DIMM)       // 3072
#define BH    (BSZ*HEADS)    // 32

// Scratch (device globals: allocation-free rule)
__device__ __nv_bfloat16 g_x_h [MROWS*DIMM], g_x_l [MROWS*DIMM];   // split x
__device__ __nv_bfloat16 g_wq_h[QKVN*DIMM],  g_wq_l[QKVN*DIMM];    // split W_qkv
__device__ __nv_bfloat16 g_wo_h[DIMM*DIMM],  g_wo_l[DIMM*DIMM];    // split W_out
__device__ __nv_bfloat16 g_q_h [BH*SEQ*HD],  g_q_l [BH*SEQ*HD];    // [bh][n][d], x1/8
__device__ __nv_bfloat16 g_k_h [BH*SEQ*HD],  g_k_l [BH*SEQ*HD];    // [bh][n][d]
__device__ __nv_bfloat16 g_vT_h[BH*HD*SEQ],  g_vT_l[BH*HD*SEQ];    // [bh][d][n]
__device__ __nv_bfloat16 g_ao_h[MROWS*DIMM], g_ao_l[MROWS*DIMM];   // [b*n][h*64+d]

// ---------------------------------------------------------------------------
// helpers
// ---------------------------------------------------------------------------
__device__ __forceinline__ uint32_t smem_u32(const void* p) {
    uint32_t a;
    asm("{ .reg .u64 t; cvta.to.shared.u64 t, %1; cvt.u32.u64 %0, t; }"
        : "=r"(a) : "l"(p));
    return a;
}
__device__ __forceinline__ void cp16(uint32_t dst, const void* src) {
    asm volatile("cp.async.cg.shared.global [%0], [%1], 16;"
                 :: "r"(dst), "l"(src) : "memory");
}
#define CP_COMMIT() asm volatile("cp.async.commit_group;" ::: "memory")
#define CP_WAIT(n)  asm volatile("cp.async.wait_group %0;" :: "n"(n) : "memory")

__device__ __forceinline__ void ldsm4(uint32_t& r0, uint32_t& r1, uint32_t& r2,
                                      uint32_t& r3, uint32_t a) {
    asm volatile("ldmatrix.sync.aligned.m8n8.x4.shared.b16 {%0,%1,%2,%3}, [%4];"
                 : "=r"(r0), "=r"(r1), "=r"(r2), "=r"(r3) : "r"(a));
}
// mma m16n8k16 bf16: D(f32) += A(bf16) * B(bf16)
__device__ __forceinline__ void mma16(float* c, const uint32_t* a, const uint32_t* b) {
    asm volatile(
        "mma.sync.aligned.m16n8k16.row.col.f32.bf16.bf16.f32 "
        "{%0,%1,%2,%3},{%4,%5,%6,%7},{%8,%9},{%0,%1,%2,%3};"
        : "+f"(c[0]), "+f"(c[1]), "+f"(c[2]), "+f"(c[3])
        : "r"(a[0]), "r"(a[1]), "r"(a[2]), "r"(a[3]), "r"(b[0]), "r"(b[1]));
}
__device__ __forceinline__ uint32_t sw128(uint32_t o) { return o ^ ((o >> 3) & 0x70); }

// pack two floats to bf16x2: x0 -> lower 16 bits (k even), x1 -> upper
__device__ __forceinline__ uint32_t packbf(float x0, float x1) {
    uint32_t d;
    asm("cvt.rn.bf16x2.f32 %0, %1, %2;" : "=r"(d) : "f"(x1), "f"(x0));
    return d;
}
// split pair: h = bf16x2(hi parts), l = bf16x2(residuals)
__device__ __forceinline__ void split2(float x0, float x1, uint32_t& h, uint32_t& l) {
    h = packbf(x0, x1);
    float f0 = __uint_as_float(h << 16);
    float f1 = __uint_as_float(h & 0xFFFF0000u);
    l = packbf(x0 - f0, x1 - f1);
}

// ---------------------------------------------------------------------------
// Pre-split: fp32 -> bf16 hi/lo planes (grid-stride over float4)
// ---------------------------------------------------------------------------
__global__ void split_kernel(const float* __restrict__ src,
                             __nv_bfloat16* __restrict__ dh,
                             __nv_bfloat16* __restrict__ dl, int n4)
{
    int i = blockIdx.x * blockDim.x + threadIdx.x;
    if (i >= n4) return;
    float4 v = ((const float4*)src)[i];
    uint32_t h0, l0, h1, l1;
    split2(v.x, v.y, h0, l0);
    split2(v.z, v.w, h1, l1);
    uint2 hh = { h0, h1 }, ll = { l0, l1 };
    ((uint2*)dh)[i] = hh;
    ((uint2*)dl)[i] = ll;
}

// ---------------------------------------------------------------------------
// 3xBF16 GEMM (pre-split inputs): C[m,e] = sum_k A[m,k]*W[e,k] + bias[e]
// 128x128 tile, K-tile 32, 4-stage cp.async, 256 threads (2x4 warps).
// SMEM stage: A rows [hi 64B | lo 64B] (128B, sw128), then B same. 32KB/stage.
// MODE 0: scatter bf16 hi/lo into g_q/g_k/g_vT.  MODE 1: C = out (fp32).
// ---------------------------------------------------------------------------
#define GSTG      32768
#define GSTAGES   4
#define GEMM_SMEM (GSTAGES * GSTG)        // 128KB (also reused as Ds 128x129 f32)

template<int MODE>
__global__ __launch_bounds__(256, 1) void gemm_tc(
    const __nv_bfloat16* __restrict__ Ah, const __nv_bfloat16* __restrict__ Al,
    const __nv_bfloat16* __restrict__ Bh, const __nv_bfloat16* __restrict__ Bl,
    const float* __restrict__ bias, float* __restrict__ C)
{
    extern __shared__ float smem_f[];
    const uint32_t base = smem_u32(smem_f);
    const int t = threadIdx.x, lane = t & 31, wid = t >> 5;
    const int wm = wid >> 2, wn = wid & 3;      // 2 x 4 warp grid
    const int m0 = blockIdx.y * 128, n0 = blockIdx.x * 128;

    auto stage_load = [&](int kt) {
        uint32_t S = base + (kt & (GSTAGES - 1)) * GSTG;
        #pragma unroll
        for (int i = 0; i < 2; i++) {
            int u = t + i * 256;                 // 0..511
            int r = u >> 2, c = u & 3;           // row, 16B col within 64B plane
            size_t ao = (size_t)(m0 + r) * DIMM + kt * 32 + c * 8;
            size_t bo = (size_t)(n0 + r) * DIMM + kt * 32 + c * 8;
            uint32_t swh = sw128((uint32_t)(r * 128 + c * 16));
            uint32_t swl = sw128((uint32_t)(r * 128 + 64 + c * 16));
            cp16(S + swh, Ah + ao);
            cp16(S + swl, Al + ao);
            cp16(S + 16384 + swh, Bh + bo);
            cp16(S + 16384 + swl, Bl + bo);
        }
        CP_COMMIT();
    };

    float acc[4][4][4];
    #pragma unroll
    for (int mt = 0; mt < 4; mt++)
        #pragma unroll
        for (int nt = 0; nt < 4; nt++)
            #pragma unroll
            for (int i = 0; i < 4; i++) acc[mt][nt][i] = 0.0f;

    stage_load(0);
    stage_load(1);
    stage_load(2);

    const int KT = DIMM / 32;   // 32
    for (int kt = 0; kt < KT; ++kt) {
        if (kt < KT - 2)       CP_WAIT(2);
        else if (kt == KT - 2) CP_WAIT(1);
        else                   CP_WAIT(0);
        __syncthreads();

        uint32_t sA = base + (kt & (GSTAGES - 1)) * GSTG, sB = sA + 16384;
        #pragma unroll
        for (int cc = 0; cc < 2; ++cc) {        // k16 chunks
            uint32_t ah[4][4], al[4][4];
            #pragma unroll
            for (int mt = 0; mt < 4; mt++) {
                int row = wm * 64 + mt * 16 + (lane & 15);
                uint32_t bc = cc * 32 + (lane >> 4) * 16;
                ldsm4(ah[mt][0], ah[mt][1], ah[mt][2], ah[mt][3],
                      sA + sw128((uint32_t)(row * 128) + bc));
                ldsm4(al[mt][0], al[mt][1], al[mt][2], al[mt][3],
                      sA + sw128((uint32_t)(row * 128) + 64 + bc));
            }
            #pragma unroll
            for (int g = 0; g < 2; g++) {       // n16 groups
                uint32_t bh4[4], bl4[4];
                int row = wn * 32 + g * 16 + (lane & 7) + ((lane & 16) ? 8 : 0);
                uint32_t bc = cc * 32 + ((lane & 8) ? 16 : 0);
                ldsm4(bh4[0], bh4[1], bh4[2], bh4[3],
                      sB + sw128((uint32_t)(row * 128) + bc));
                ldsm4(bl4[0], bl4[1], bl4[2], bl4[3],
                      sB + sw128((uint32_t)(row * 128) + 64 + bc));
                #pragma unroll
                for (int mt = 0; mt < 4; mt++) {
                    mma16(acc[mt][2*g],     ah[mt], bh4);
                    mma16(acc[mt][2*g],     al[mt], bh4);
                    mma16(acc[mt][2*g],     ah[mt], bl4);
                    mma16(acc[mt][2*g + 1], ah[mt], bh4 + 2);
                    mma16(acc[mt][2*g + 1], al[mt], bh4 + 2);
                    mma16(acc[mt][2*g + 1], ah[mt], bl4 + 2);
                }
            }
        }
        if (kt + 3 < KT) stage_load(kt + 3);
    }

    // ------------------------------ epilogue ------------------------------
    const int r  = lane >> 2;
    const int c2 = (lane & 3) * 2;

    if (MODE == 1) {
        #pragma unroll
        for (int mt = 0; mt < 4; mt++) {
            int m = m0 + wm * 64 + mt * 16 + r;
            #pragma unroll
            for (int nt = 0; nt < 4; nt++) {
                int e = n0 + wn * 32 + nt * 8 + c2;
                float2 bb = *(const float2*)&bias[e];
                float2 v0 = { acc[mt][nt][0] + bb.x, acc[mt][nt][1] + bb.y };
                float2 v1 = { acc[mt][nt][2] + bb.x, acc[mt][nt][3] + bb.y };
                *(float2*)&C[(size_t)m * DIMM + e]       = v0;
                *(float2*)&C[(size_t)(m + 8) * DIMM + e] = v1;
            }
        }
    } else {
        const int part = n0 >> 10;              // 0=q 1=k 2=v
        if (part < 2) {
            __nv_bfloat16* dh = part ? g_k_h : g_q_h;
            __nv_bfloat16* dl = part ? g_k_l : g_q_l;
            const float sc = part ? 1.0f : 0.125f;
            #pragma unroll
            for (int mt = 0; mt < 4; mt++) {
                int m = m0 + wm * 64 + mt * 16 + r;
                int bb_ = m >> 11, nloc = m & 2047;
                #pragma unroll
                for (int nt = 0; nt < 4; nt++) {
                    int eg = n0 + wn * 32 + nt * 8 + c2;
                    float2 bv = *(const float2*)&bias[eg];
                    int e = eg & 1023;
                    int h = e >> 6, d = e & 63;
                    size_t o = ((size_t)((bb_ * HEADS + h) * SEQ + nloc)) * HD + d;
                    uint32_t hh, ll;
                    split2((acc[mt][nt][0] + bv.x) * sc, (acc[mt][nt][1] + bv.y) * sc, hh, ll);
                    *(uint32_t*)&dh[o] = hh;
                    *(uint32_t*)&dl[o] = ll;
                    split2((acc[mt][nt][2] + bv.x) * sc, (acc[mt][nt][3] + bv.y) * sc, hh, ll);
                    *(uint32_t*)&dh[o + 8 * HD] = hh;
                    *(uint32_t*)&dl[o + 8 * HD] = ll;
                }
            }
        } else {
            // v: bounce fp32 via smem, transpose, split to g_vT hi/lo [d][n]
            float* Ds = smem_f;                  // [128][129]
            __syncthreads();
            #pragma unroll
            for (int mt = 0; mt < 4; mt++) {
                int ml = wm * 64 + mt * 16 + r;
                #pragma unroll
                for (int nt = 0; nt < 4; nt++) {
                    int el = wn * 32 + nt * 8 + c2;
                    float2 bv = *(const float2*)&bias[n0 + el];
                    Ds[ml * 129 + el]           = acc[mt][nt][0] + bv.x;
                    Ds[ml * 129 + el + 1]       = acc[mt][nt][1] + bv.y;
                    Ds[(ml + 8) * 129 + el]     = acc[mt][nt][2] + bv.x;
                    Ds[(ml + 8) * 129 + el + 1] = acc[mt][nt][3] + bv.y;
                }
            }
            __syncthreads();
            int e  = t >> 1;                     // d index within tile (0..127)
            int mh = (t & 1) * 64;               // n half
            int dg = (n0 & 1023) + e;
            int h = dg >> 6, d = dg & 63;
            int bb_ = m0 >> 11, nloc = m0 & 2047;
            size_t ob = ((size_t)((bb_ * HEADS + h) * HD + d)) * SEQ + nloc + mh;
            #pragma unroll 4
            for (int i = 0; i < 64; i += 4) {
                uint32_t h0, l0, h1, l1;
                split2(Ds[(mh + i) * 129 + e],     Ds[(mh + i + 1) * 129 + e], h0, l0);
                split2(Ds[(mh + i + 2) * 129 + e], Ds[(mh + i + 3) * 129 + e], h1, l1);
                uint2 vh = { h0, h1 }, vl = { l0, l1 };
                *(uint2*)&g_vT_h[ob + i] = vh;
                *(uint2*)&g_vT_l[ob + i] = vl;
            }
        }
    }
}

// ---------------------------------------------------------------------------
// Flash attention, 3xBF16. CTA = 64 q-rows (4 warps, m16/warp), j-tile 64.
// SMEM planes (all [64 rows][128B], sw128): Qh, Ql; per stage: Kh, Kl, Vh, Vl.
// Epilogue writes g_ao pre-split bf16 hi/lo.
// ---------------------------------------------------------------------------
#define F_SMEM (16384 + 2 * 32768)   // 80KB

__global__ __launch_bounds__(128) void flash_kernel()
{
    extern __shared__ float fs[];
    const uint32_t base = smem_u32(fs);
    const uint32_t Qh = base, Ql = base + 8192;
    const uint32_t St = base + 16384;            // stages

    const int t = threadIdx.x, lane = t & 31, w = t >> 5;
    const int bh = blockIdx.x, i0 = blockIdx.y;
    const int r = lane >> 2, q = lane & 3;

    // Q tile (once)
    {
        const __nv_bfloat16* qh = g_q_h + ((size_t)bh * SEQ + i0 * 64) * HD;
        const __nv_bfloat16* ql = g_q_l + ((size_t)bh * SEQ + i0 * 64) * HD;
        #pragma unroll
        for (int i = 0; i < 4; i++) {
            int u = t + i * 128;
            int rr = u >> 3, c = u & 7;
            uint32_t sw = sw128((uint32_t)(rr * 128 + c * 16));
            cp16(Qh + sw, qh + (size_t)rr * HD + c * 8);
            cp16(Ql + sw, ql + (size_t)rr * HD + c * 8);
        }
        CP_COMMIT();
    }
    auto loadKV = [&](int j) {
        uint32_t S = St + (j & 1) * 32768;
        const __nv_bfloat16* kh = g_k_h  + ((size_t)bh * SEQ + j * 64) * HD;
        const __nv_bfloat16* kl = g_k_l  + ((size_t)bh * SEQ + j * 64) * HD;
        const __nv_bfloat16* vh = g_vT_h + (size_t)bh * HD * SEQ + j * 64;
        const __nv_bfloat16* vl = g_vT_l + (size_t)bh * HD * SEQ + j * 64;
        #pragma unroll
        for (int i = 0; i < 4; i++) {
            int u = t + i * 128;
            int rr = u >> 3, c = u & 7;
            uint32_t sw = sw128((uint32_t)(rr * 128 + c * 16));
            cp16(S + sw,         kh + (size_t)rr * HD + c * 8);
            cp16(S + 8192 + sw,  kl + (size_t)rr * HD + c * 8);
            cp16(S + 16384 + sw, vh + (size_t)rr * SEQ + c * 8);
            cp16(S + 24576 + sw, vl + (size_t)rr * SEQ + c * 8);
        }
        CP_COMMIT();
    };
    loadKV(0);

    float oacc[8][4];
    #pragma unroll
    for (int d = 0; d < 8; d++)
        #pragma unroll
        for (int i = 0; i < 4; i++) oacc[d][i] = 0.0f;
    float mrow[2] = { -CUDART_INF_F, -CUDART_INF_F };
    float lrow[2] = { 0.0f, 0.0f };

    for (int j = 0; j < SEQ / 64; ++j) {
        if (j + 1 < SEQ / 64) { loadKV(j + 1); CP_WAIT(1); }
        else                  { CP_WAIT(0); }
        __syncthreads();
        const uint32_t sK = St + (j & 1) * 32768;
        const uint32_t sV = sK + 16384;

        // ---- S = Q K^T (scale folded into Q), 3xBF16 ----
        float sacc[8][4];
        #pragma unroll
        for (int nt = 0; nt < 8; nt++)
            #pragma unroll
            for (int i = 0; i < 4; i++) sacc[nt][i] = 0.0f;

        #pragma unroll
        for (int cc = 0; cc < 4; ++cc) {        // k16 over d=64
            uint32_t ah[4], al[4];
            {
                int row = w * 16 + (lane & 15);
                uint32_t bc = cc * 32 + (lane >> 4) * 16;
                ldsm4(ah[0], ah[1], ah[2], ah[3], Qh + sw128((uint32_t)(row * 128) + bc));
                ldsm4(al[0], al[1], al[2], al[3], Ql + sw128((uint32_t)(row * 128) + bc));
            }
            #pragma unroll
            for (int g = 0; g < 4; g++) {       // n16 over 64 keys
                uint32_t bh4[4], bl4[4];
                int row = g * 16 + (lane & 7) + ((lane & 16) ? 8 : 0);
                uint32_t bc = cc * 32 + ((lane & 8) ? 16 : 0);
                ldsm4(bh4[0], bh4[1], bh4[2], bh4[3],
                      sK + sw128((uint32_t)(row * 128) + bc));
                ldsm4(bl4[0], bl4[1], bl4[2], bl4[3],
                      sK + 8192 + sw128((uint32_t)(row * 128) + bc));
                mma16(sacc[2*g],     ah, bh4);
                mma16(sacc[2*g],     al, bh4);
                mma16(sacc[2*g],     ah, bl4);
                mma16(sacc[2*g + 1], ah, bh4 + 2);
                mma16(sacc[2*g + 1], al, bh4 + 2);
                mma16(sacc[2*g + 1], ah, bl4 + 2);
            }
        }

        // ---- online softmax ----
        #pragma unroll
        for (int rp = 0; rp < 2; rp++) {
            const int lo = rp * 2;
            float mx = -CUDART_INF_F;
            #pragma unroll
            for (int nt = 0; nt < 8; nt++)
                mx = fmaxf(mx, fmaxf(sacc[nt][lo], sacc[nt][lo + 1]));
            mx = fmaxf(mx, __shfl_xor_sync(0xffffffffu, mx, 1));
            mx = fmaxf(mx, __shfl_xor_sync(0xffffffffu, mx, 2));
            float mn = fmaxf(mrow[rp], mx);
            float corr = __expf(mrow[rp] - mn);
            mrow[rp] = mn;
            float sum = 0.0f;
            #pragma unroll
            for (int nt = 0; nt < 8; nt++) {
                float p0 = __expf(sacc[nt][lo] - mn);
                float p1 = __expf(sacc[nt][lo + 1] - mn);
                sacc[nt][lo] = p0; sacc[nt][lo + 1] = p1;
                sum += p0 + p1;
            }
            sum += __shfl_xor_sync(0xffffffffu, sum, 1);
            sum += __shfl_xor_sync(0xffffffffu, sum, 2);
            lrow[rp] = lrow[rp] * corr + sum;
            #pragma unroll
            for (int d = 0; d < 8; d++) {
                oacc[d][lo]     *= corr;
                oacc[d][lo + 1] *= corr;
            }
        }

        // ---- O += P V  (P split to bf16 hi/lo in-register) ----
        #pragma unroll
        for (int kc = 0; kc < 4; ++kc) {        // k16 over 64 keys
            uint32_t ph[4], pl[4];
            split2(sacc[2*kc][0],     sacc[2*kc][1],     ph[0], pl[0]);
            split2(sacc[2*kc][2],     sacc[2*kc][3],     ph[1], pl[1]);
            split2(sacc[2*kc + 1][0], sacc[2*kc + 1][1], ph[2], pl[2]);
            split2(sacc[2*kc + 1][2], sacc[2*kc + 1][3], ph[3], pl[3]);
            #pragma unroll
            for (int g = 0; g < 4; g++) {       // n16 over d=64
                uint32_t vh4[4], vl4[4];
                int row = g * 16 + (lane & 7) + ((lane & 16) ? 8 : 0);
                uint32_t bc = kc * 32 + ((lane & 8) ? 16 : 0);
                ldsm4(vh4[0], vh4[1], vh4[2], vh4[3],
                      sV + sw128((uint32_t)(row * 128) + bc));
                ldsm4(vl4[0], vl4[1], vl4[2], vl4[3],
                      sV + 8192 + sw128((uint32_t)(row * 128) + bc));
                mma16(oacc[2*g],     ph, vh4);
                mma16(oacc[2*g],     pl, vh4);
                mma16(oacc[2*g],     ph, vl4);
                mma16(oacc[2*g + 1], ph, vh4 + 2);
                mma16(oacc[2*g + 1], pl, vh4 + 2);
                mma16(oacc[2*g + 1], ph, vl4 + 2);
            }
        }
        __syncthreads();
    }

    // ---- write O pre-split (bf16 hi/lo planes) ----
    const int bb = bh >> 4, h = bh & 15;
    #pragma unroll
    for (int rp = 0; rp < 2; rp++) {
        float inv = 1.0f / lrow[rp];
        int n = i0 * 64 + w * 16 + r + rp * 8;
        size_t ob = ((size_t)(bb * SEQ + n)) * DIMM + h * 64;
        #pragma unroll
        for (int d = 0; d < 8; d++) {
            uint32_t hh, ll;
            split2(oacc[d][rp * 2] * inv, oacc[d][rp * 2 + 1] * inv, hh, ll);
            *(uint32_t*)&g_ao_h[ob + d * 8 + q * 2] = hh;
            *(uint32_t*)&g_ao_l[ob + d * 8 + q * 2] = ll;
        }
    }
}

// ---------------------------------------------------------------------------
extern "C" void kernel_launch(void* const* d_in, const int* in_sizes, int n_in,
                              void* d_out, int out_size)
{
    const float* x     = (const float*)d_in[0];
    const float* W_qkv = (const float*)d_in[1];
    const float* b_qkv = (const float*)d_in[2];
    const float* W_out = (const float*)d_in[3];
    const float* b_out = (const float*)d_in[4];
    float* out = (float*)d_out;

    cudaFuncSetAttribute(gemm_tc<0>, cudaFuncAttributeMaxDynamicSharedMemorySize, GEMM_SMEM);
    cudaFuncSetAttribute(gemm_tc<1>, cudaFuncAttributeMaxDynamicSharedMemorySize, GEMM_SMEM);
    cudaFuncSetAttribute(flash_kernel, cudaFuncAttributeMaxDynamicSharedMemorySize, F_SMEM);

    __nv_bfloat16 *xh, *xl, *wqh, *wql, *woh, *wol;
    cudaGetSymbolAddress((void**)&xh,  g_x_h);  cudaGetSymbolAddress((void**)&xl,  g_x_l);
    cudaGetSymbolAddress((void**)&wqh, g_wq_h); cudaGetSymbolAddress((void**)&wql, g_wq_l);
    cudaGetSymbolAddress((void**)&woh, g_wo_h); cudaGetSymbolAddress((void**)&wol, g_wo_l);
    __nv_bfloat16 *aoh, *aol;
    cudaGetSymbolAddress((void**)&aoh, g_ao_h); cudaGetSymbolAddress((void**)&aol, g_ao_l);

    split_kernel<<<(MROWS*DIMM/4 + 255)/256, 256>>>(x,     xh,  xl,  MROWS*DIMM/4);
    split_kernel<<<(QKVN*DIMM/4 + 255)/256, 256>>>(W_qkv, wqh, wql, QKVN*DIMM/4);
    split_kernel<<<(DIMM*DIMM/4 + 255)/256, 256>>>(W_out, woh, wol, DIMM*DIMM/4);

    gemm_tc<0><<<dim3(QKVN/128, MROWS/128), 256, GEMM_SMEM>>>(xh, xl, wqh, wql, b_qkv, nullptr);
    flash_kernel<<<dim3(BH, SEQ/64), 128, F_SMEM>>>();
    gemm_tc<1><<<dim3(DIMM/128, MROWS/128), 256, GEMM_SMEM>>>(aoh, aol, woh, wol, b_out, out);
}